// round 15
// baseline (speedup 1.0000x reference)
#include <cuda_runtime.h>
#include <cstdint>

// Degenerate BiLSTM: h=c=0 => only emb[:,S-1] (fwd) and emb[:,0] (bwd) matter;
// f-gate dead; Whf/Whb unused.  B=128, S=2048, EMB=128, HID=256, OUT=32.
//
// R13 skeleton (measured best: 12.8us) + release/poll shaves:
// Grid 160 = 128 workers (32 h-chunks x 4 batch-groups) + 32 head blocks.
// Worker: W tile via cp.async.bulk; x gathered 2-threads-per-row into 132-word
// padded rows (CF LDS.128); GEMV with fma.rn.f32x2, 2 h x 3 gates per warp;
// fwd/bwd stored to separate g_hyA/g_hyB; PER-WARP red.release on wcnt
// (no block sync, no threadfence, no tid0 serialization).
// Head (8 per bg, 4 batches each): stages Why[o][k] (260-pad) during worker
// phase; ALL-THREAD acquire-poll on wcnt (no post-poll barrier); staging adds
// hyA+hyB; vectorized float4 GEMV; 32-wide log-softmax.

#define NB_B   128
#define NB_S   2048
#define NB_EMB 128
#define NB_HID 256
#define NB_OUT 32

__device__ unsigned int g_wcnt[4];            // +256 per launch per bg (warps)
__device__ unsigned int g_hcnt[4];            // +8   per launch per bg (heads)
__device__ float        g_hyA[NB_HID * NB_B]; // fwd  [h][b]
__device__ float        g_hyB[NB_HID * NB_B]; // bwd  [h][b]

// dynamic smem byte offsets (worker / head overlays)
#define SM_XS    0              // worker: xs 8448 fl | head: Why_s 8320 fl
#define SM_WSM   33792          // worker: W 24576 B  | head: hy_s 4*260 fl
#define SM_RED2  37952          // head: red2 4*33 floats (528 B)
#define SM_MBAR  59424          // 8 B
#define SMEM_BYTES 59456

__device__ __forceinline__ float fsigm(float x) {
    return __fdividef(1.0f, 1.0f + __expf(-x));
}
__device__ __forceinline__ float ftanh(float x) {
    float r; asm("tanh.approx.f32 %0, %1;" : "=f"(r) : "f"(x)); return r;
}
__device__ __forceinline__ unsigned int smem_u32(const void* p) {
    unsigned int a;
    asm("{ .reg .u64 t; cvta.to.shared.u64 t, %1; cvt.u32.u64 %0, t; }"
        : "=r"(a) : "l"(p));
    return a;
}
__device__ __forceinline__ unsigned long long fma2(
    unsigned long long a, unsigned long long b, unsigned long long c) {
    unsigned long long d;
    asm("fma.rn.f32x2 %0, %1, %2, %3;" : "=l"(d) : "l"(a), "l"(b), "l"(c));
    return d;
}
__device__ __forceinline__ void lds_v2b64(unsigned int a,
                                          unsigned long long& x,
                                          unsigned long long& y) {
    asm volatile("ld.shared.v2.b64 {%0, %1}, [%2];" : "=l"(x), "=l"(y) : "r"(a));
}
__device__ __forceinline__ float acc_sum(unsigned long long v) {
    return __uint_as_float((unsigned int)v) + __uint_as_float((unsigned int)(v >> 32));
}
__device__ __forceinline__ void mbar_wait0(unsigned int mbar) {
    unsigned int done;
    asm volatile(
        "{\n\t.reg .pred p;\n\t"
        "mbarrier.try_wait.parity.acquire.cta.shared::cta.b64 p, [%1], 0;\n\t"
        "selp.b32 %0, 1, 0, p;\n\t}"
        : "=r"(done) : "r"(mbar) : "memory");
    if (!done) {
        asm volatile(
            "{\n\t.reg .pred P1;\n\t"
            "WL_%=:\n\t"
            "mbarrier.try_wait.parity.acquire.cta.shared::cta.b64 P1, [%0], 0, 0x989680;\n\t"
            "@P1 bra.uni WD_%=;\n\t"
            "bra.uni WL_%=;\n\t"
            "WD_%=:\n\t}"
            :: "r"(mbar) : "memory");
    }
}

__global__ void __launch_bounds__(256, 1) bilstm_kernel(
    const int*   __restrict__ inputs,   // [B, S]
    const float* __restrict__ weight,   // [VOCAB, EMB]
    const float* __restrict__ Wxf,      // [1024, 128]
    const float* __restrict__ bxf,
    const float* __restrict__ bhf,
    const float* __restrict__ Wxb,
    const float* __restrict__ bxb,
    const float* __restrict__ bhb,
    const float* __restrict__ Why,      // [32, 256]
    const float* __restrict__ by,       // [32]
    float*       __restrict__ out)      // [B, 32]
{
    extern __shared__ char dsm[];
    const int tid = threadIdx.x;
    const int bid = blockIdx.x;

    if (bid < 128) {
        // ================= WORKER =================
        const int hc     = bid & 31;
        const int bg     = bid >> 5;
        const int h_base = hc * 8;
        const int b_base = bg * 32;

        float* xs = (float*)(dsm + SM_XS);     // [dir*4224 + lb*132 + e]
        const unsigned int sb   = smem_u32(dsm);
        const unsigned int mbar = sb + SM_MBAR;

        // --- parallel staging ---
        if (tid < 128) {
            // 2 threads per (dir,lb) row; each copies 64 floats (16 float4).
            const int row  = tid >> 1;
            const int half = tid & 1;
            const int dir  = row >> 5;
            const int lb   = row & 31;
            const int tok  = inputs[(b_base + lb) * NB_S + (dir ? 0 : (NB_S - 1))];
            const float4* src = (const float4*)(weight + tok * NB_EMB + half * 64);
            float* dst = xs + dir * 4224 + lb * 132 + half * 64;
            #pragma unroll
            for (int e4 = 0; e4 < 16; e4++)
                *(float4*)(dst + e4 * 4) = src[e4];
        } else if (tid == 128) {
            asm volatile("mbarrier.init.shared.b64 [%0], 1;" :: "r"(mbar) : "memory");
            asm volatile("mbarrier.arrive.expect_tx.shared.b64 _, [%0], %1;"
                         :: "r"(mbar), "r"(24576u) : "memory");
            const int goff[3] = {0, 512, 768};
            #pragma unroll
            for (int c = 0; c < 6; c++) {
                const float* src = (c >= 3 ? Wxb : Wxf)
                                 + (goff[c % 3] + h_base) * NB_EMB;
                const unsigned int dst = sb + SM_WSM + c * 4096;
                asm volatile(
                    "cp.async.bulk.shared::cluster.global.mbarrier::complete_tx::bytes "
                    "[%0], [%1], %2, [%3];"
                    :: "r"(dst), "l"(src), "r"(4096u), "r"(mbar) : "memory");
            }
        }

        const int w   = tid >> 5;      // 8 warps
        const int lb  = tid & 31;      // lane = batch
        const int dir = w >> 2;        // 0 fwd / 1 bwd
        const int hp  = w & 3;         // h-pair

        // Bias sums (warp-uniform; c=0 => bx + bh only). 3 gates x 2 h.
        const float* bx = dir ? bxb : bxf;
        const float* bh = dir ? bhb : bhf;
        float bias[6];
        #pragma unroll
        for (int g = 0; g < 3; g++) {
            const int go = (g == 0 ? 0 : (g == 1 ? 512 : 768));
            #pragma unroll
            for (int j = 0; j < 2; j++) {
                const int h = h_base + 2 * hp + j;
                bias[g * 2 + j] = bx[go + h] + bh[go + h];
            }
        }

        __syncthreads();      // xs ready
        mbar_wait0(mbar);     // W tile ready

        // GEMV: per k4: 1 x LDS.128 (CF, stride 132) + 6 broadcast W LDS.128
        // + 12 FMA2.
        unsigned int wrow[6];
        #pragma unroll
        for (int g = 0; g < 3; g++)
            #pragma unroll
            for (int j = 0; j < 2; j++)
                wrow[g * 2 + j] = sb + SM_WSM
                                + (((dir * 3 + g) * 8) + 2 * hp + j) * 512;

        const unsigned int xaddr = sb + SM_XS + (dir * 4224 + lb * 132) * 4;

        unsigned long long acc[6] = {0ull, 0ull, 0ull, 0ull, 0ull, 0ull};
        #pragma unroll 8
        for (int k4 = 0; k4 < 32; k4++) {
            unsigned long long xa, xb;
            lds_v2b64(xaddr + k4 * 16, xa, xb);
            #pragma unroll
            for (int r = 0; r < 6; r++) {
                unsigned long long w01, w23;
                lds_v2b64(wrow[r] + k4 * 16, w01, w23);
                acc[r] = fma2(w01, xa, acc[r]);
                acc[r] = fma2(w23, xb, acc[r]);
            }
        }

        // Store each dir's hy, then per-warp release (orders prior stores).
        float* g_hy = dir ? g_hyB : g_hyA;
        #pragma unroll
        for (int j = 0; j < 2; j++) {
            const float gi = acc_sum(acc[0 * 2 + j]) + bias[0 * 2 + j];
            const float gg = acc_sum(acc[1 * 2 + j]) + bias[1 * 2 + j];
            const float go = acc_sum(acc[2 * 2 + j]) + bias[2 * 2 + j];
            const float hyv = fsigm(go) * ftanh(fsigm(gi) * ftanh(gg));
            g_hy[(h_base + 2 * hp + j) * NB_B + b_base + lb] = hyv;
        }
        __syncwarp();
        if (lb == 0) {
            asm volatile("red.release.gpu.global.add.u32 [%0], 1;"
                         :: "l"(&g_wcnt[bg]) : "memory");
        }
    } else {
        // ================= HEAD (32 blocks, 4 batches each) =================
        const int hb = bid - 128;        // 0..31
        const int bg = hb >> 3;
        const int q  = hb & 7;
        const int b0 = bg * 32 + q * 4;

        float* Why_s = (float*)(dsm + SM_XS);    // [o*260 + k]  (CF LDS.128)
        float* hy_s  = (float*)(dsm + SM_WSM);   // [bl*260 + k] (broadcast)
        float* red2  = (float*)(dsm + SM_RED2);  // [bl*33 + o]

        // Hoist by (off the post-poll critical path).
        const float by_r = by[tid & 31];

        // Stage Why during the worker phase.
        #pragma unroll
        for (int it = 0; it < 32; it++) {
            const int idx = tid + it * 256;      // 8192
            const int o = idx >> 8;
            const int k = idx & 255;
            Why_s[o * 260 + k] = Why[idx];
        }

        // Epoch-safe wait, ALL threads poll (no post-poll barrier).
        // N = hcnt/8 (this block hasn't incremented; peers add <8 before end);
        // wait until wcnt >= 256*(N+1)  (32 blocks x 8 warps per bg).
        {
            unsigned int h0;
            asm volatile("ld.global.relaxed.gpu.u32 %0, [%1];"
                         : "=r"(h0) : "l"(&g_hcnt[bg]));
            const unsigned int target = ((h0 >> 3) + 1u) * 256u;
            unsigned int v;
            do {
                asm volatile("ld.global.acquire.gpu.u32 %0, [%1];"
                             : "=r"(v) : "l"(&g_wcnt[bg]) : "memory");
                if ((int)(v - target) >= 0) break;
                __nanosleep(16);
            } while (true);
        }

        // Stage hy for 4 batches (1024 floats): add the two dir buffers.
        #pragma unroll
        for (int it = 0; it < 4; it++) {
            const int idx = tid + it * 256;
            const int bl  = idx & 3;
            const int k   = idx >> 2;
            const int g   = k * NB_B + b0 + bl;
            hy_s[bl * 260 + k] = __ldcg(&g_hyA[g]) + __ldcg(&g_hyB[g]);
        }
        __syncthreads();

        // warp = (bl, k-half); lane = output o. 32 float4-iters:
        // 1 broadcast hy LDS.128 + 1 CF Why LDS.128 + 4 FMA.
        const int o  = tid & 31;
        const int w  = tid >> 5;
        const int bl = w & 3;
        const int kh = w >> 2;
        const float4* hy4 = (const float4*)(hy_s + bl * 260 + kh * 128);
        const float4* wy4 = (const float4*)(Why_s + o * 260 + kh * 128);

        float a0 = 0.f, a1 = 0.f, a2 = 0.f, a3 = 0.f;
        #pragma unroll 8
        for (int k4 = 0; k4 < 32; k4++) {
            const float4 hv = hy4[k4];
            const float4 wv = wy4[k4];
            a0 = fmaf(hv.x, wv.x, a0);
            a1 = fmaf(hv.y, wv.y, a1);
            a2 = fmaf(hv.z, wv.z, a2);
            a3 = fmaf(hv.w, wv.w, a3);
        }
        const float part = (a0 + a1) + (a2 + a3);

        if (kh == 1) red2[bl * 33 + o] = part;
        __syncthreads();
        if (kh == 0) {
            const float acc = part + red2[bl * 33 + o] + by_r;
            float mx = acc;
            #pragma unroll
            for (int off = 16; off; off >>= 1)
                mx = fmaxf(mx, __shfl_xor_sync(0xffffffffu, mx, off));
            float s = __expf(acc - mx);
            #pragma unroll
            for (int off = 16; off; off >>= 1)
                s += __shfl_xor_sync(0xffffffffu, s, off);
            out[(b0 + bl) * NB_OUT + o] = acc - mx - __logf(s);
        }

        __syncthreads();
        if (tid == 0) atomicAdd(&g_hcnt[bg], 1u);
    }
}

// Inputs in metadata order:
// 0 inputs(int32) 1 weight 2 Wxf 3 bxf 4 Whf(unused) 5 bhf
// 6 Wxb 7 bxb 8 Whb(unused) 9 bhb 10 Why 11 by
extern "C" void kernel_launch(void* const* d_in, const int* in_sizes, int n_in,
                              void* d_out, int out_size)
{
    const int*   inputs = (const int*)  d_in[0];
    const float* weight = (const float*)d_in[1];
    const float* Wxf    = (const float*)d_in[2];
    const float* bxf    = (const float*)d_in[3];
    const float* bhf    = (const float*)d_in[5];
    const float* Wxb    = (const float*)d_in[6];
    const float* bxb    = (const float*)d_in[7];
    const float* bhb    = (const float*)d_in[9];
    const float* Why    = (const float*)d_in[10];
    const float* by     = (const float*)d_in[11];
    float*       out    = (float*)d_out;

    static int configured = 0;
    if (!configured) {
        cudaFuncSetAttribute(bilstm_kernel,
                             cudaFuncAttributeMaxDynamicSharedMemorySize,
                             SMEM_BYTES);
        configured = 1;
    }

    bilstm_kernel<<<160, 256, SMEM_BYTES>>>(inputs, weight, Wxf, bxf, bhf,
                                            Wxb, bxb, bhb, Why, by, out);
}

// round 16
// speedup vs baseline: 1.1414x; 1.1414x over previous
#include <cuda_runtime.h>
#include <cstdint>

// Degenerate BiLSTM: h=c=0 => only emb[:,S-1] (fwd) and emb[:,0] (bwd) matter;
// f-gate dead; Whf/Whb unused.  B=128, S=2048, EMB=128, HID=256, OUT=32.
//
// R13 skeleton (measured best: 12.8us) + interleaved hy layout:
// Grid 160 = 128 workers (32 h-chunks x 4 batch-groups) + 32 head blocks.
// Worker: W tile via cp.async.bulk; x gathered 2-threads-per-row into 132-word
// padded rows (CF LDS.128); GEMV with fma.rn.f32x2, 2 h x 3 gates per warp;
// fwd/bwd stored interleaved g_hy[(h*128+b)*2+dir]; block release
// (sync + threadfence + tid0 atomicAdd) -- measured best protocol.
// Head (8 per bg, 4 batches each): stages Why[o][k] (260-pad) during worker
// phase; tid0 epoch-safe poll + sync; staging = 8 float2 LDG.64/thread
// (both dirs in one load, summed in-register); vectorized float4 GEMV;
// 32-wide log-softmax.

#define NB_B   128
#define NB_S   2048
#define NB_EMB 128
#define NB_HID 256
#define NB_OUT 32

__device__ unsigned int g_wcnt[4];            // +32 per launch per bg (workers)
__device__ unsigned int g_hcnt[4];            // +8  per launch per bg (heads)
__device__ float        g_hy[NB_HID * NB_B * 2];  // [h][b][dir] interleaved

// dynamic smem byte offsets (worker / head overlays)
#define SM_XS    0              // worker: xs 8448 fl | head: Why_s 8320 fl
#define SM_WSM   33792          // worker: W 24576 B  | head: hy_s 4*260 fl
#define SM_RED2  37952          // head: red2 4*33 floats (528 B)
#define SM_MBAR  59424          // 8 B
#define SMEM_BYTES 59456

__device__ __forceinline__ float fsigm(float x) {
    return __fdividef(1.0f, 1.0f + __expf(-x));
}
__device__ __forceinline__ float ftanh(float x) {
    float r; asm("tanh.approx.f32 %0, %1;" : "=f"(r) : "f"(x)); return r;
}
__device__ __forceinline__ unsigned int smem_u32(const void* p) {
    unsigned int a;
    asm("{ .reg .u64 t; cvta.to.shared.u64 t, %1; cvt.u32.u64 %0, t; }"
        : "=r"(a) : "l"(p));
    return a;
}
__device__ __forceinline__ unsigned long long fma2(
    unsigned long long a, unsigned long long b, unsigned long long c) {
    unsigned long long d;
    asm("fma.rn.f32x2 %0, %1, %2, %3;" : "=l"(d) : "l"(a), "l"(b), "l"(c));
    return d;
}
__device__ __forceinline__ void lds_v2b64(unsigned int a,
                                          unsigned long long& x,
                                          unsigned long long& y) {
    asm volatile("ld.shared.v2.b64 {%0, %1}, [%2];" : "=l"(x), "=l"(y) : "r"(a));
}
__device__ __forceinline__ float acc_sum(unsigned long long v) {
    return __uint_as_float((unsigned int)v) + __uint_as_float((unsigned int)(v >> 32));
}
__device__ __forceinline__ void mbar_wait0(unsigned int mbar) {
    unsigned int done;
    asm volatile(
        "{\n\t.reg .pred p;\n\t"
        "mbarrier.try_wait.parity.acquire.cta.shared::cta.b64 p, [%1], 0;\n\t"
        "selp.b32 %0, 1, 0, p;\n\t}"
        : "=r"(done) : "r"(mbar) : "memory");
    if (!done) {
        asm volatile(
            "{\n\t.reg .pred P1;\n\t"
            "WL_%=:\n\t"
            "mbarrier.try_wait.parity.acquire.cta.shared::cta.b64 P1, [%0], 0, 0x989680;\n\t"
            "@P1 bra.uni WD_%=;\n\t"
            "bra.uni WL_%=;\n\t"
            "WD_%=:\n\t}"
            :: "r"(mbar) : "memory");
    }
}

__global__ void __launch_bounds__(256, 1) bilstm_kernel(
    const int*   __restrict__ inputs,   // [B, S]
    const float* __restrict__ weight,   // [VOCAB, EMB]
    const float* __restrict__ Wxf,      // [1024, 128]
    const float* __restrict__ bxf,
    const float* __restrict__ bhf,
    const float* __restrict__ Wxb,
    const float* __restrict__ bxb,
    const float* __restrict__ bhb,
    const float* __restrict__ Why,      // [32, 256]
    const float* __restrict__ by,       // [32]
    float*       __restrict__ out)      // [B, 32]
{
    extern __shared__ char dsm[];
    const int tid = threadIdx.x;
    const int bid = blockIdx.x;

    if (bid < 128) {
        // ================= WORKER =================
        const int hc     = bid & 31;
        const int bg     = bid >> 5;
        const int h_base = hc * 8;
        const int b_base = bg * 32;

        float* xs = (float*)(dsm + SM_XS);     // [dir*4224 + lb*132 + e]
        const unsigned int sb   = smem_u32(dsm);
        const unsigned int mbar = sb + SM_MBAR;

        // --- parallel staging ---
        if (tid < 128) {
            // 2 threads per (dir,lb) row; each copies 64 floats (16 float4).
            const int row  = tid >> 1;
            const int half = tid & 1;
            const int dir  = row >> 5;
            const int lb   = row & 31;
            const int tok  = inputs[(b_base + lb) * NB_S + (dir ? 0 : (NB_S - 1))];
            const float4* src = (const float4*)(weight + tok * NB_EMB + half * 64);
            float* dst = xs + dir * 4224 + lb * 132 + half * 64;
            #pragma unroll
            for (int e4 = 0; e4 < 16; e4++)
                *(float4*)(dst + e4 * 4) = src[e4];
        } else if (tid == 128) {
            asm volatile("mbarrier.init.shared.b64 [%0], 1;" :: "r"(mbar) : "memory");
            asm volatile("mbarrier.arrive.expect_tx.shared.b64 _, [%0], %1;"
                         :: "r"(mbar), "r"(24576u) : "memory");
            const int goff[3] = {0, 512, 768};
            #pragma unroll
            for (int c = 0; c < 6; c++) {
                const float* src = (c >= 3 ? Wxb : Wxf)
                                 + (goff[c % 3] + h_base) * NB_EMB;
                const unsigned int dst = sb + SM_WSM + c * 4096;
                asm volatile(
                    "cp.async.bulk.shared::cluster.global.mbarrier::complete_tx::bytes "
                    "[%0], [%1], %2, [%3];"
                    :: "r"(dst), "l"(src), "r"(4096u), "r"(mbar) : "memory");
            }
        }

        const int w   = tid >> 5;      // 8 warps
        const int lb  = tid & 31;      // lane = batch
        const int dir = w >> 2;        // 0 fwd / 1 bwd
        const int hp  = w & 3;         // h-pair

        // Bias sums (warp-uniform; c=0 => bx + bh only). 3 gates x 2 h.
        const float* bx = dir ? bxb : bxf;
        const float* bh = dir ? bhb : bhf;
        float bias[6];
        #pragma unroll
        for (int g = 0; g < 3; g++) {
            const int go = (g == 0 ? 0 : (g == 1 ? 512 : 768));
            #pragma unroll
            for (int j = 0; j < 2; j++) {
                const int h = h_base + 2 * hp + j;
                bias[g * 2 + j] = bx[go + h] + bh[go + h];
            }
        }

        __syncthreads();      // xs ready
        mbar_wait0(mbar);     // W tile ready

        // GEMV: per k4: 1 x LDS.128 (CF, stride 132) + 6 broadcast W LDS.128
        // + 12 FMA2.
        unsigned int wrow[6];
        #pragma unroll
        for (int g = 0; g < 3; g++)
            #pragma unroll
            for (int j = 0; j < 2; j++)
                wrow[g * 2 + j] = sb + SM_WSM
                                + (((dir * 3 + g) * 8) + 2 * hp + j) * 512;

        const unsigned int xaddr = sb + SM_XS + (dir * 4224 + lb * 132) * 4;

        unsigned long long acc[6] = {0ull, 0ull, 0ull, 0ull, 0ull, 0ull};
        #pragma unroll 8
        for (int k4 = 0; k4 < 32; k4++) {
            unsigned long long xa, xb;
            lds_v2b64(xaddr + k4 * 16, xa, xb);
            #pragma unroll
            for (int r = 0; r < 6; r++) {
                unsigned long long w01, w23;
                lds_v2b64(wrow[r] + k4 * 16, w01, w23);
                acc[r] = fma2(w01, xa, acc[r]);
                acc[r] = fma2(w23, xb, acc[r]);
            }
        }

        // Store each dir's hy into the interleaved buffer (no combine).
        #pragma unroll
        for (int j = 0; j < 2; j++) {
            const float gi = acc_sum(acc[0 * 2 + j]) + bias[0 * 2 + j];
            const float gg = acc_sum(acc[1 * 2 + j]) + bias[1 * 2 + j];
            const float go = acc_sum(acc[2 * 2 + j]) + bias[2 * 2 + j];
            const float hyv = fsigm(go) * ftanh(fsigm(gi) * ftanh(gg));
            g_hy[((h_base + 2 * hp + j) * NB_B + b_base + lb) * 2 + dir] = hyv;
        }

        __syncthreads();      // all warps' stores issued
        if (tid == 0) {
            __threadfence();
            atomicAdd(&g_wcnt[bg], 1u);
        }
    } else {
        // ================= HEAD (32 blocks, 4 batches each) =================
        const int hb = bid - 128;        // 0..31
        const int bg = hb >> 3;
        const int q  = hb & 7;
        const int b0 = bg * 32 + q * 4;

        float* Why_s = (float*)(dsm + SM_XS);    // [o*260 + k]  (CF LDS.128)
        float* hy_s  = (float*)(dsm + SM_WSM);   // [bl*260 + k] (broadcast)
        float* red2  = (float*)(dsm + SM_RED2);  // [bl*33 + o]

        // Hoist by (off the post-poll critical path).
        const float by_r = by[tid & 31];

        // Stage Why during the worker phase.
        #pragma unroll
        for (int it = 0; it < 32; it++) {
            const int idx = tid + it * 256;      // 8192
            const int o = idx >> 8;
            const int k = idx & 255;
            Why_s[o * 260 + k] = Why[idx];
        }

        // Epoch-safe wait: N = hcnt/8 (this block hasn't incremented yet);
        // wait until wcnt >= 32*(N+1).
        if (tid == 0) {
            unsigned int h0;
            asm volatile("ld.global.relaxed.gpu.u32 %0, [%1];"
                         : "=r"(h0) : "l"(&g_hcnt[bg]));
            const unsigned int target = ((h0 >> 3) + 1u) * 32u;
            unsigned int v;
            do {
                asm volatile("ld.global.acquire.gpu.u32 %0, [%1];"
                             : "=r"(v) : "l"(&g_wcnt[bg]) : "memory");
                if ((int)(v - target) >= 0) break;
                __nanosleep(16);
            } while (true);
        }
        __syncthreads();

        // Stage hy for 4 batches: 1024 float2 loads (both dirs per load).
        #pragma unroll
        for (int it = 0; it < 4; it++) {
            const int idx = tid + it * 256;
            const int bl  = idx & 3;
            const int k   = idx >> 2;
            const float2 v = __ldcg((const float2*)&g_hy[(k * NB_B + b0 + bl) * 2]);
            hy_s[bl * 260 + k] = v.x + v.y;
        }
        __syncthreads();

        // warp = (bl, k-half); lane = output o. 32 float4-iters:
        // 1 broadcast hy LDS.128 + 1 CF Why LDS.128 + 4 FMA.
        const int o  = tid & 31;
        const int w  = tid >> 5;
        const int bl = w & 3;
        const int kh = w >> 2;
        const float4* hy4 = (const float4*)(hy_s + bl * 260 + kh * 128);
        const float4* wy4 = (const float4*)(Why_s + o * 260 + kh * 128);

        float a0 = 0.f, a1 = 0.f, a2 = 0.f, a3 = 0.f;
        #pragma unroll 8
        for (int k4 = 0; k4 < 32; k4++) {
            const float4 hv = hy4[k4];
            const float4 wv = wy4[k4];
            a0 = fmaf(hv.x, wv.x, a0);
            a1 = fmaf(hv.y, wv.y, a1);
            a2 = fmaf(hv.z, wv.z, a2);
            a3 = fmaf(hv.w, wv.w, a3);
        }
        const float part = (a0 + a1) + (a2 + a3);

        if (kh == 1) red2[bl * 33 + o] = part;
        __syncthreads();
        if (kh == 0) {
            const float acc = part + red2[bl * 33 + o] + by_r;
            float mx = acc;
            #pragma unroll
            for (int off = 16; off; off >>= 1)
                mx = fmaxf(mx, __shfl_xor_sync(0xffffffffu, mx, off));
            float s = __expf(acc - mx);
            #pragma unroll
            for (int off = 16; off; off >>= 1)
                s += __shfl_xor_sync(0xffffffffu, s, off);
            out[(b0 + bl) * NB_OUT + o] = acc - mx - __logf(s);
        }

        __syncthreads();
        if (tid == 0) atomicAdd(&g_hcnt[bg], 1u);
    }
}

// Inputs in metadata order:
// 0 inputs(int32) 1 weight 2 Wxf 3 bxf 4 Whf(unused) 5 bhf
// 6 Wxb 7 bxb 8 Whb(unused) 9 bhb 10 Why 11 by
extern "C" void kernel_launch(void* const* d_in, const int* in_sizes, int n_in,
                              void* d_out, int out_size)
{
    const int*   inputs = (const int*)  d_in[0];
    const float* weight = (const float*)d_in[1];
    const float* Wxf    = (const float*)d_in[2];
    const float* bxf    = (const float*)d_in[3];
    const float* bhf    = (const float*)d_in[5];
    const float* Wxb    = (const float*)d_in[6];
    const float* bxb    = (const float*)d_in[7];
    const float* bhb    = (const float*)d_in[9];
    const float* Why    = (const float*)d_in[10];
    const float* by     = (const float*)d_in[11];
    float*       out    = (float*)d_out;

    static int configured = 0;
    if (!configured) {
        cudaFuncSetAttribute(bilstm_kernel,
                             cudaFuncAttributeMaxDynamicSharedMemorySize,
                             SMEM_BYTES);
        configured = 1;
    }

    bilstm_kernel<<<160, 256, SMEM_BYTES>>>(inputs, weight, Wxf, bxf, bhf,
                                            Wxb, bxb, bhb, Why, by, out);
}

// round 17
// speedup vs baseline: 1.1473x; 1.0052x over previous
#include <cuda_runtime.h>
#include <cstdint>

// Degenerate BiLSTM: h=c=0 => only emb[:,S-1] (fwd) and emb[:,0] (bwd) matter;
// f-gate dead; Whf/Whb unused.  B=128, S=2048, EMB=128, HID=256, OUT=32.
//
// R15 skeleton (measured best: 12.45us) + DMA x-gather:
// Grid 160 = 128 workers (32 h-chunks x 4 batch-groups) + 32 head blocks.
// Worker: ONE mbarrier covers x and W. tid0 init + expect_tx(57344);
// early sync publishes init; tid<64: token LDG -> 512B cp.async.bulk of the
// embedding row into its padded xs slot; tid128: 6x4KB W bulk copies.
// GEMV gates on mbar only (pre-GEMV __syncthreads deleted): per k4
// 1 CF x LDS.128 + 6 broadcast W LDS.128 + 12 fma.rn.f32x2, 2 h x 3 gates
// per warp; fwd/bwd stored interleaved g_hy[(h*128+b)*2+dir]; block release
// (sync + threadfence + tid0 atomicAdd).
// Head (8 per bg, 4 batches): stages Why[o][k] (260-pad) during worker phase;
// tid0 epoch-safe poll + sync; staging = float2 loads (both dirs per load);
// vectorized float4 GEMV; 32-wide log-softmax.

#define NB_B   128
#define NB_S   2048
#define NB_EMB 128
#define NB_HID 256
#define NB_OUT 32

__device__ unsigned int g_wcnt[4];            // +32 per launch per bg (workers)
__device__ unsigned int g_hcnt[4];            // +8  per launch per bg (heads)
__device__ float        g_hy[NB_HID * NB_B * 2];  // [h][b][dir] interleaved

// dynamic smem byte offsets (worker / head overlays)
#define SM_XS    0              // worker: xs 8448 fl | head: Why_s 8320 fl
#define SM_WSM   33792          // worker: W 24576 B  | head: hy_s 4*260 fl
#define SM_RED2  37952          // head: red2 4*33 floats (528 B)
#define SM_MBAR  59424          // 8 B
#define SMEM_BYTES 59456

// total DMA bytes into the worker block: x 64*512 + W 6*4096
#define WORKER_TX (64u * 512u + 24576u)

__device__ __forceinline__ float fsigm(float x) {
    return __fdividef(1.0f, 1.0f + __expf(-x));
}
__device__ __forceinline__ float ftanh(float x) {
    float r; asm("tanh.approx.f32 %0, %1;" : "=f"(r) : "f"(x)); return r;
}
__device__ __forceinline__ unsigned int smem_u32(const void* p) {
    unsigned int a;
    asm("{ .reg .u64 t; cvta.to.shared.u64 t, %1; cvt.u32.u64 %0, t; }"
        : "=r"(a) : "l"(p));
    return a;
}
__device__ __forceinline__ unsigned long long fma2(
    unsigned long long a, unsigned long long b, unsigned long long c) {
    unsigned long long d;
    asm("fma.rn.f32x2 %0, %1, %2, %3;" : "=l"(d) : "l"(a), "l"(b), "l"(c));
    return d;
}
__device__ __forceinline__ void lds_v2b64(unsigned int a,
                                          unsigned long long& x,
                                          unsigned long long& y) {
    asm volatile("ld.shared.v2.b64 {%0, %1}, [%2];" : "=l"(x), "=l"(y) : "r"(a));
}
__device__ __forceinline__ float acc_sum(unsigned long long v) {
    return __uint_as_float((unsigned int)v) + __uint_as_float((unsigned int)(v >> 32));
}
__device__ __forceinline__ void bulk_g2s(unsigned int dst, const void* src,
                                         unsigned int bytes, unsigned int mbar) {
    asm volatile(
        "cp.async.bulk.shared::cluster.global.mbarrier::complete_tx::bytes "
        "[%0], [%1], %2, [%3];"
        :: "r"(dst), "l"(src), "r"(bytes), "r"(mbar) : "memory");
}
__device__ __forceinline__ void mbar_wait0(unsigned int mbar) {
    unsigned int done;
    asm volatile(
        "{\n\t.reg .pred p;\n\t"
        "mbarrier.try_wait.parity.acquire.cta.shared::cta.b64 p, [%1], 0;\n\t"
        "selp.b32 %0, 1, 0, p;\n\t}"
        : "=r"(done) : "r"(mbar) : "memory");
    if (!done) {
        asm volatile(
            "{\n\t.reg .pred P1;\n\t"
            "WL_%=:\n\t"
            "mbarrier.try_wait.parity.acquire.cta.shared::cta.b64 P1, [%0], 0, 0x989680;\n\t"
            "@P1 bra.uni WD_%=;\n\t"
            "bra.uni WL_%=;\n\t"
            "WD_%=:\n\t}"
            :: "r"(mbar) : "memory");
    }
}

__global__ void __launch_bounds__(256, 1) bilstm_kernel(
    const int*   __restrict__ inputs,   // [B, S]
    const float* __restrict__ weight,   // [VOCAB, EMB]
    const float* __restrict__ Wxf,      // [1024, 128]
    const float* __restrict__ bxf,
    const float* __restrict__ bhf,
    const float* __restrict__ Wxb,
    const float* __restrict__ bxb,
    const float* __restrict__ bhb,
    const float* __restrict__ Why,      // [32, 256]
    const float* __restrict__ by,       // [32]
    float*       __restrict__ out)      // [B, 32]
{
    extern __shared__ char dsm[];
    const int tid = threadIdx.x;
    const int bid = blockIdx.x;

    if (bid < 128) {
        // ================= WORKER =================
        const int hc     = bid & 31;
        const int bg     = bid >> 5;
        const int h_base = hc * 8;
        const int b_base = bg * 32;

        const unsigned int sb   = smem_u32(dsm);
        const unsigned int mbar = sb + SM_MBAR;

        // mbar init + total expect_tx, published by a cheap early sync.
        if (tid == 0) {
            asm volatile("mbarrier.init.shared.b64 [%0], 1;" :: "r"(mbar) : "memory");
            asm volatile("mbarrier.arrive.expect_tx.shared.b64 _, [%0], %1;"
                         :: "r"(mbar), "r"(WORKER_TX) : "memory");
        }
        __syncthreads();

        // --- all staging is DMA ---
        if (tid < 64) {
            // Own (dir, lb) row: token LDG -> 512B bulk copy into padded slot.
            const int dir = tid >> 5;
            const int lb  = tid & 31;
            const int tok = inputs[(b_base + lb) * NB_S + (dir ? 0 : (NB_S - 1))];
            bulk_g2s(sb + SM_XS + (dir * 4224 + lb * 132) * 4,
                     weight + tok * NB_EMB, 512u, mbar);
        } else if (tid == 64) {
            const int goff[3] = {0, 512, 768};
            #pragma unroll
            for (int c = 0; c < 6; c++) {
                const float* src = (c >= 3 ? Wxb : Wxf)
                                 + (goff[c % 3] + h_base) * NB_EMB;
                bulk_g2s(sb + SM_WSM + c * 4096, src, 4096u, mbar);
            }
        }

        const int w   = tid >> 5;      // 8 warps
        const int lb  = tid & 31;      // lane = batch
        const int dir = w >> 2;        // 0 fwd / 1 bwd
        const int hp  = w & 3;         // h-pair

        // Bias sums (warp-uniform; c=0 => bx + bh only). 3 gates x 2 h.
        const float* bx = dir ? bxb : bxf;
        const float* bh = dir ? bhb : bhf;
        float bias[6];
        #pragma unroll
        for (int g = 0; g < 3; g++) {
            const int go = (g == 0 ? 0 : (g == 1 ? 512 : 768));
            #pragma unroll
            for (int j = 0; j < 2; j++) {
                const int h = h_base + 2 * hp + j;
                bias[g * 2 + j] = bx[go + h] + bh[go + h];
            }
        }

        mbar_wait0(mbar);     // x + W tiles ready (no block barrier needed)

        // GEMV: per k4: 1 x LDS.128 (CF, stride 132) + 6 broadcast W LDS.128
        // + 12 FMA2.
        unsigned int wrow[6];
        #pragma unroll
        for (int g = 0; g < 3; g++)
            #pragma unroll
            for (int j = 0; j < 2; j++)
                wrow[g * 2 + j] = sb + SM_WSM
                                + (((dir * 3 + g) * 8) + 2 * hp + j) * 512;

        const unsigned int xaddr = sb + SM_XS + (dir * 4224 + lb * 132) * 4;

        unsigned long long acc[6] = {0ull, 0ull, 0ull, 0ull, 0ull, 0ull};
        #pragma unroll 8
        for (int k4 = 0; k4 < 32; k4++) {
            unsigned long long xa, xb;
            lds_v2b64(xaddr + k4 * 16, xa, xb);
            #pragma unroll
            for (int r = 0; r < 6; r++) {
                unsigned long long w01, w23;
                lds_v2b64(wrow[r] + k4 * 16, w01, w23);
                acc[r] = fma2(w01, xa, acc[r]);
                acc[r] = fma2(w23, xb, acc[r]);
            }
        }

        // Store each dir's hy into the interleaved buffer (no combine).
        #pragma unroll
        for (int j = 0; j < 2; j++) {
            const float gi = acc_sum(acc[0 * 2 + j]) + bias[0 * 2 + j];
            const float gg = acc_sum(acc[1 * 2 + j]) + bias[1 * 2 + j];
            const float go = acc_sum(acc[2 * 2 + j]) + bias[2 * 2 + j];
            const float hyv = fsigm(go) * ftanh(fsigm(gi) * ftanh(gg));
            g_hy[((h_base + 2 * hp + j) * NB_B + b_base + lb) * 2 + dir] = hyv;
        }

        __syncthreads();      // all warps' stores issued
        if (tid == 0) {
            __threadfence();
            atomicAdd(&g_wcnt[bg], 1u);
        }
    } else {
        // ================= HEAD (32 blocks, 4 batches each) =================
        const int hb = bid - 128;        // 0..31
        const int bg = hb >> 3;
        const int q  = hb & 7;
        const int b0 = bg * 32 + q * 4;

        float* Why_s = (float*)(dsm + SM_XS);    // [o*260 + k]  (CF LDS.128)
        float* hy_s  = (float*)(dsm + SM_WSM);   // [bl*260 + k] (broadcast)
        float* red2  = (float*)(dsm + SM_RED2);  // [bl*33 + o]

        // Hoist by (off the post-poll critical path).
        const float by_r = by[tid & 31];

        // Stage Why during the worker phase.
        #pragma unroll
        for (int it = 0; it < 32; it++) {
            const int idx = tid + it * 256;      // 8192
            const int o = idx >> 8;
            const int k = idx & 255;
            Why_s[o * 260 + k] = Why[idx];
        }

        // Epoch-safe wait: N = hcnt/8 (this block hasn't incremented yet);
        // wait until wcnt >= 32*(N+1).
        if (tid == 0) {
            unsigned int h0;
            asm volatile("ld.global.relaxed.gpu.u32 %0, [%1];"
                         : "=r"(h0) : "l"(&g_hcnt[bg]));
            const unsigned int target = ((h0 >> 3) + 1u) * 32u;
            unsigned int v;
            do {
                asm volatile("ld.global.acquire.gpu.u32 %0, [%1];"
                             : "=r"(v) : "l"(&g_wcnt[bg]) : "memory");
                if ((int)(v - target) >= 0) break;
                __nanosleep(16);
            } while (true);
        }
        __syncthreads();

        // Stage hy for 4 batches: 1024 float2 loads (both dirs per load).
        #pragma unroll
        for (int it = 0; it < 4; it++) {
            const int idx = tid + it * 256;
            const int bl  = idx & 3;
            const int k   = idx >> 2;
            const float2 v = __ldcg((const float2*)&g_hy[(k * NB_B + b0 + bl) * 2]);
            hy_s[bl * 260 + k] = v.x + v.y;
        }
        __syncthreads();

        // warp = (bl, k-half); lane = output o. 32 float4-iters:
        // 1 broadcast hy LDS.128 + 1 CF Why LDS.128 + 4 FMA.
        const int o  = tid & 31;
        const int w  = tid >> 5;
        const int bl = w & 3;
        const int kh = w >> 2;
        const float4* hy4 = (const float4*)(hy_s + bl * 260 + kh * 128);
        const float4* wy4 = (const float4*)(Why_s + o * 260 + kh * 128);

        float a0 = 0.f, a1 = 0.f, a2 = 0.f, a3 = 0.f;
        #pragma unroll 8
        for (int k4 = 0; k4 < 32; k4++) {
            const float4 hv = hy4[k4];
            const float4 wv = wy4[k4];
            a0 = fmaf(hv.x, wv.x, a0);
            a1 = fmaf(hv.y, wv.y, a1);
            a2 = fmaf(hv.z, wv.z, a2);
            a3 = fmaf(hv.w, wv.w, a3);
        }
        const float part = (a0 + a1) + (a2 + a3);

        if (kh == 1) red2[bl * 33 + o] = part;
        __syncthreads();
        if (kh == 0) {
            const float acc = part + red2[bl * 33 + o] + by_r;
            float mx = acc;
            #pragma unroll
            for (int off = 16; off; off >>= 1)
                mx = fmaxf(mx, __shfl_xor_sync(0xffffffffu, mx, off));
            float s = __expf(acc - mx);
            #pragma unroll
            for (int off = 16; off; off >>= 1)
                s += __shfl_xor_sync(0xffffffffu, s, off);
            out[(b0 + bl) * NB_OUT + o] = acc - mx - __logf(s);
        }

        __syncthreads();
        if (tid == 0) atomicAdd(&g_hcnt[bg], 1u);
    }
}

// Inputs in metadata order:
// 0 inputs(int32) 1 weight 2 Wxf 3 bxf 4 Whf(unused) 5 bhf
// 6 Wxb 7 bxb 8 Whb(unused) 9 bhb 10 Why 11 by
extern "C" void kernel_launch(void* const* d_in, const int* in_sizes, int n_in,
                              void* d_out, int out_size)
{
    const int*   inputs = (const int*)  d_in[0];
    const float* weight = (const float*)d_in[1];
    const float* Wxf    = (const float*)d_in[2];
    const float* bxf    = (const float*)d_in[3];
    const float* bhf    = (const float*)d_in[5];
    const float* Wxb    = (const float*)d_in[6];
    const float* bxb    = (const float*)d_in[7];
    const float* bhb    = (const float*)d_in[9];
    const float* Why    = (const float*)d_in[10];
    const float* by     = (const float*)d_in[11];
    float*       out    = (float*)d_out;

    static int configured = 0;
    if (!configured) {
        cudaFuncSetAttribute(bilstm_kernel,
                             cudaFuncAttributeMaxDynamicSharedMemorySize,
                             SMEM_BYTES);
        configured = 1;
    }

    bilstm_kernel<<<160, 256, SMEM_BYTES>>>(inputs, weight, Wxf, bxf, bhf,
                                            Wxb, bxb, bhb, Why, by, out);
}